// round 10
// baseline (speedup 1.0000x reference)
#include <cuda_runtime.h>
#include <cuda_bf16.h>
#include <cstdint>

// ============================================================================
// Problem constants
// ============================================================================
static constexpr int N = 8192;
static constexpr int D = 512;
static constexpr int BM = 128;              // rows per CTA tile
static constexpr int BN = 128;              // cols per CTA tile
static constexpr int BK = 64;               // k per stage
static constexpr int STAGES = 4;
static constexpr int CTILES = N / BN;       // 64 column tiles
static constexpr int NTRI = CTILES * (CTILES + 1) / 2;  // 2080 upper-tri tiles

static constexpr float CEXP = 20.609929365128333f;      // (1/T)*log2(e), T=0.07

// ============================================================================
// Device scratch (static — no allocation allowed)
// ============================================================================
__device__ __align__(16) __nv_bfloat16 g_fn[N * D];     // normalized features, bf16
__device__ int   g_card[N];
__device__ float g_Spos[CTILES * N];                    // per-(coltile,row) partials
__device__ float g_Sneg[CTILES * N];
__device__ float g_Sp2[4 * N];                          // final-reduce stage
__device__ float g_Sn2[4 * N];
__device__ float g_red[64];

// ============================================================================
// Helpers (baseline sm_80+ PTX only — NO tcgen05, target is plain sm_103)
// ============================================================================
__device__ __forceinline__ uint32_t smem_u32(const void* p) {
    uint32_t a;
    asm("{ .reg .u64 t; cvta.to.shared.u64 t, %1; cvt.u32.u64 %0, t; }"
        : "=r"(a) : "l"(p));
    return a;
}

__device__ __forceinline__ float ex2f(float x) {
    float y; asm("ex2.approx.ftz.f32 %0, %1;" : "=f"(y) : "f"(x)); return y;
}

#define SW128(o) ((o) ^ (((o) >> 3) & 0x70))

__device__ __forceinline__ void cp16(uint32_t saddr, const void* g) {
    asm volatile("cp.async.cg.shared.global [%0], [%1], 16;"
                 :: "r"(saddr), "l"(g) : "memory");
}

__device__ __forceinline__ void ldsm4(uint32_t* r, uint32_t addr) {
    asm volatile("ldmatrix.sync.aligned.m8n8.x4.shared.b16 {%0,%1,%2,%3}, [%4];"
                 : "=r"(r[0]), "=r"(r[1]), "=r"(r[2]), "=r"(r[3]) : "r"(addr));
}

__device__ __forceinline__ void mma16816(float* c, const uint32_t* a,
                                         uint32_t b0, uint32_t b1) {
    asm volatile(
        "mma.sync.aligned.m16n8k16.row.col.f32.bf16.bf16.f32 "
        "{%0,%1,%2,%3}, {%4,%5,%6,%7}, {%8,%9}, {%0,%1,%2,%3};"
        : "+f"(c[0]), "+f"(c[1]), "+f"(c[2]), "+f"(c[3])
        : "r"(a[0]), "r"(a[1]), "r"(a[2]), "r"(a[3]), "r"(b0), "r"(b1));
}

// ============================================================================
// Kernel A: row-normalize features -> bf16 (+ zero g_card for this replay)
// ============================================================================
__global__ void __launch_bounds__(256) k_normalize(const float* __restrict__ f) {
    int row = blockIdx.x, tid = threadIdx.x;
    float a = f[row * D + tid];
    float b = f[row * D + 256 + tid];
    float s = a * a + b * b;
    for (int o = 16; o; o >>= 1) s += __shfl_xor_sync(~0u, s, o);
    __shared__ float red[8];
    __shared__ float s_inv;
    if ((tid & 31) == 0) red[tid >> 5] = s;
    __syncthreads();
    if (tid == 0) {
        float t = 0.f;
        #pragma unroll
        for (int i = 0; i < 8; i++) t += red[i];
        float n = fmaxf(sqrtf(t), 1e-8f);
        s_inv = 1.0f / n;
        g_card[row] = 0;                      // reset for k_main's atomics
    }
    __syncthreads();
    float inv = s_inv;
    g_fn[row * D + tid]       = __float2bfloat16(a * inv);
    g_fn[row * D + 256 + tid] = __float2bfloat16(b * inv);
}

// ============================================================================
// Kernel M: upper-triangle GEMM tiles with mask bitpack FUSED into the
//   mainloop (loads issued before the MMA block, ballots after it -> latency
//   hidden under tensor work). Off-diag tiles run a normal epilogue AND a
//   smem-transposed one (p_ij == p_ji; masks are asymmetric).
//   grid NTRI=2080 linear -> (bi <= bj). 256 threads, 8 warps (4m x 2n).
// ============================================================================
static constexpr uint32_t STAGE_BYTES = 32768;          // A 16KB + B 16KB
static constexpr uint32_t OFF_SA = 0;
static constexpr uint32_t OFF_SB = 16384;
static constexpr uint32_t OFF_RED  = STAGES * STAGE_BYTES;     // 131072 (1KB)
static constexpr uint32_t OFF_BITS = OFF_RED + 1024;           // 132096 (8KB)
static constexpr uint32_t SMEM_BYTES = OFF_BITS + 8192;        // 140288
static constexpr int TP = 132;                          // transpose row pitch (floats)

__device__ __forceinline__ void stage_copy(uint32_t sbase, int tid,
                                           int rowbase, int colbase, int kt) {
    const int k0 = kt * BK;
    #pragma unroll
    for (int i = 0; i < 4; i++) {
        int seg = i * 256 + tid;             // 1024 x 16B segs per tile
        int r = seg >> 3, c = seg & 7;       // 128 rows x 8 x 16B (128B/row)
        uint32_t so = SW128((uint32_t)(r * 128 + c * 16));
        cp16(sbase + OFF_SA + so, g_fn + (size_t)(rowbase + r) * D + k0 + c * 8);
        cp16(sbase + OFF_SB + so, g_fn + (size_t)(colbase + r) * D + k0 + c * 8);
    }
}

__global__ void __launch_bounds__(256, 1) k_main(const int* __restrict__ posm,
                                                 const int* __restrict__ negm) {
    extern __shared__ char smem[];
    const uint32_t smem_base = smem_u32(smem);
    const int tid  = threadIdx.x;
    const int lane = tid & 31;
    const int wid  = tid >> 5;
    const int warp_m = wid & 3;              // 4 warps along m
    const int warp_n = wid >> 2;             // 2 warps along n

    // decode linear tile id -> (bi, bj), bi <= bj
    int t = blockIdx.x;
    int bi = (int)(0.5f * (129.0f - sqrtf(16641.0f - 8.0f * (float)t)));
    while (64 * (bi + 1) - ((bi + 1) * bi) / 2 <= t) bi++;
    while (64 * bi - (bi * (bi - 1)) / 2 > t) bi--;
    const int bj = bi + (t - (64 * bi - (bi * (bi - 1)) / 2));
    const int rowbase = bi * BM;
    const int colbase = bj * BN;
    const bool offdiag = (bi != bj);

    float* sP = reinterpret_cast<float*>(smem + OFF_RED);
    float* sN = sP + 128;
    unsigned* sbits = reinterpret_cast<unsigned*>(smem + OFF_BITS);
    // layout: sbits[(orient*2+mask)*512 + row*4 + w]; orient0 = rows bi/cols bj
    if (tid < 128) { sP[tid] = 0.f; sN[tid] = 0.f; }

    // prologue: fill STAGES-1 stages
    #pragma unroll
    for (int s = 0; s < STAGES - 1; s++) {
        stage_copy(smem_base + s * STAGE_BYTES, tid, rowbase, colbase, s);
        asm volatile("cp.async.commit_group;" ::: "memory");
    }

    float acc[2][8][4];
    #pragma unroll
    for (int mi = 0; mi < 2; mi++)
        #pragma unroll
        for (int nj = 0; nj < 8; nj++)
            #pragma unroll
            for (int q = 0; q < 4; q++) acc[mi][nj][q] = 0.f;

    const int la_row  = warp_m * 32 + (lane & 15);   // A ldmatrix row
    const int lb_row  = warp_n * 64 + (lane & 15);   // B ldmatrix row
    const int l_khalf = (lane >> 4) * 16;            // k-half byte offset

    // fused bitpack: off-diag 2048 words / diag 1024 words, split over
    // 8 kt x 8 warps; per-slot 32 (off-diag) or 16 (diag) words.
    const int nw_slot = offdiag ? 32 : 16;

    #pragma unroll 1
    for (int kt = 0; kt < D / BK; kt++) {
        asm volatile("cp.async.wait_group %0;" :: "n"(STAGES - 2) : "memory");
        __syncthreads();

        if (kt + STAGES - 1 < D / BK) {
            stage_copy(smem_base + ((kt + STAGES - 1) % STAGES) * STAGE_BYTES,
                       tid, rowbase, colbase, kt + STAGES - 1);
        }
        asm volatile("cp.async.commit_group;" ::: "memory");

        // ---- fused mask loads (independent LDGs; consumed after MMAs) ----
        int mv[32];
        const int slot = kt * 8 + wid;
        #pragma unroll
        for (int i = 0; i < 32; i++) {
            if (i < nw_slot) {
                int widx = slot * nw_slot + i;
                int orient = offdiag ? (widx >> 10) : 0;
                int rem  = widx & (offdiag ? 1023 : 1023);
                int msk  = (offdiag ? (rem >> 9) : (widx >> 9)) & 1;
                int rem2 = widx & 511;
                int row  = rem2 >> 2, w = rem2 & 3;
                const int* m = msk ? negm : posm;
                size_t ga = orient
                    ? (size_t)(colbase + row) * N + rowbase + w * 32 + lane
                    : (size_t)(rowbase + row) * N + colbase + w * 32 + lane;
                mv[i] = m[ga];
            }
        }

        const uint32_t sa = smem_base + (kt % STAGES) * STAGE_BYTES + OFF_SA;
        const uint32_t sb = smem_base + (kt % STAGES) * STAGE_BYTES + OFF_SB;

        #pragma unroll
        for (int kk = 0; kk < BK / 16; kk++) {
            uint32_t a[2][4], b[4][4];
            #pragma unroll
            for (int mi = 0; mi < 2; mi++)
                ldsm4(a[mi], sa + SW128((uint32_t)((la_row + mi * 16) * 128 +
                                                   kk * 32 + l_khalf)));
            #pragma unroll
            for (int np = 0; np < 4; np++)
                ldsm4(b[np], sb + SW128((uint32_t)((lb_row + np * 16) * 128 +
                                                   kk * 32 + l_khalf)));
            #pragma unroll
            for (int mi = 0; mi < 2; mi++)
                #pragma unroll
                for (int nj = 0; nj < 8; nj++)
                    mma16816(acc[mi][nj], a[mi],
                             b[nj >> 1][(nj & 1)], b[nj >> 1][(nj & 1) + 2]);
        }

        // ---- ballots (loads have had ~the MMA block to land) ----
        #pragma unroll
        for (int i = 0; i < 32; i++) {
            if (i < nw_slot) {
                int widx = slot * nw_slot + i;
                int orient = offdiag ? (widx >> 10) : 0;
                int msk  = offdiag ? ((widx >> 9) & 1) : (widx >> 9);
                int rem2 = widx & 511;
                int row  = rem2 >> 2, w = rem2 & 3;
                unsigned bset = __ballot_sync(~0u, mv[i] != 0);
                if (!offdiag && (row >> 5) == w) bset &= ~(1u << (row & 31));
                if (lane == 0)
                    sbits[(orient * 2 + msk) * 512 + row * 4 + w] = bset;
            }
        }
    }
    __syncthreads();      // sbits complete across warps

    // ------------------------------------------------------------------
    // Convert accumulators to p = exp((sim-1)/T) in place
    // ------------------------------------------------------------------
    #pragma unroll
    for (int mi = 0; mi < 2; mi++)
        #pragma unroll
        for (int nj = 0; nj < 8; nj++)
            #pragma unroll
            for (int q = 0; q < 4; q++)
                acc[mi][nj][q] = ex2f(fmaf(acc[mi][nj][q], CEXP, -CEXP));

    // ------------------------------------------------------------------
    // Normal epilogue: masked row sums for rows of block bi, cols block bj
    // ------------------------------------------------------------------
    #pragma unroll
    for (int mi = 0; mi < 2; mi++) {
        #pragma unroll
        for (int rsel = 0; rsel < 2; rsel++) {
            const int lrow = warp_m * 32 + mi * 16 + (lane >> 2) + rsel * 8;
            const uint2 pw = *reinterpret_cast<const uint2*>(
                &sbits[0 * 512 + lrow * 4 + warp_n * 2]);
            const uint2 nw = *reinterpret_cast<const uint2*>(
                &sbits[1 * 512 + lrow * 4 + warp_n * 2]);
            float sp = 0.f, sn = 0.f;
            #pragma unroll
            for (int nj = 0; nj < 8; nj++) {
                #pragma unroll
                for (int u = 0; u < 2; u++) {
                    float p = acc[mi][nj][rsel * 2 + u];
                    int c64 = nj * 8 + (lane & 3) * 2 + u;
                    unsigned pword = (c64 < 32) ? pw.x : pw.y;
                    unsigned nword = (c64 < 32) ? nw.x : nw.y;
                    sp = fmaf(p, (float)((pword >> (c64 & 31)) & 1u), sp);
                    sn = fmaf(p, (float)((nword >> (c64 & 31)) & 1u), sn);
                }
            }
            sp += __shfl_xor_sync(~0u, sp, 1);
            sp += __shfl_xor_sync(~0u, sp, 2);
            sn += __shfl_xor_sync(~0u, sn, 1);
            sn += __shfl_xor_sync(~0u, sn, 2);
            if ((lane & 3) == 0) {   // 2 commutative adds per addr -> deterministic
                atomicAdd(&sP[lrow], sp);
                atomicAdd(&sN[lrow], sn);
                atomicAdd(&g_card[rowbase + lrow],
                          __popc(pw.x) + __popc(pw.y));   // int: deterministic
            }
        }
    }
    asm volatile("cp.async.wait_group 0;" ::: "memory");
    __syncthreads();     // stage smem reads done; sP/sN complete
    if (tid < 128) {
        g_Spos[(size_t)bj * N + rowbase + tid] = sP[tid];
        g_Sneg[(size_t)bj * N + rowbase + tid] = sN[tid];
    }

    // ------------------------------------------------------------------
    // Transposed epilogue (off-diagonal tiles): p_ij == p_ji — this tile
    // also provides cols of block bi for rows of block bj.
    // ------------------------------------------------------------------
    if (offdiag) {
        float* tf = reinterpret_cast<float*>(smem);     // reuse stage area
        #pragma unroll
        for (int mi = 0; mi < 2; mi++)
            #pragma unroll
            for (int rsel = 0; rsel < 2; rsel++) {
                const int r = warp_m * 32 + mi * 16 + (lane >> 2) + rsel * 8;
                #pragma unroll
                for (int nj = 0; nj < 8; nj++)
                    #pragma unroll
                    for (int u = 0; u < 2; u++) {
                        const int c = warp_n * 64 + nj * 8 + (lane & 3) * 2 + u;
                        tf[c * TP + r] = acc[mi][nj][rsel * 2 + u];
                    }
            }
        __syncthreads();
        if (tid < 128) {
            const int c = tid;
            const int gcol = colbase + c;
            const uint4 pw4 = *reinterpret_cast<const uint4*>(&sbits[2 * 512 + c * 4]);
            const uint4 nw4 = *reinterpret_cast<const uint4*>(&sbits[3 * 512 + c * 4]);
            const unsigned pws[4] = {pw4.x, pw4.y, pw4.z, pw4.w};
            const unsigned nws[4] = {nw4.x, nw4.y, nw4.z, nw4.w};
            const float* pf = tf + c * TP;
            float sp = 0.f, sn = 0.f;
            #pragma unroll
            for (int w = 0; w < 4; w++) {
                const unsigned pword = pws[w], nword = nws[w];
                #pragma unroll 8
                for (int b = 0; b < 32; b++) {
                    float p = pf[w * 32 + b];
                    sp = fmaf(p, (float)((pword >> b) & 1u), sp);
                    sn = fmaf(p, (float)((nword >> b) & 1u), sn);
                }
            }
            g_Spos[(size_t)bi * N + gcol] = sp;
            g_Sneg[(size_t)bi * N + gcol] = sn;
            atomicAdd(&g_card[gcol],
                      __popc(pws[0]) + __popc(pws[1]) +
                      __popc(pws[2]) + __popc(pws[3]));
        }
    }
}

// ============================================================================
// Final reduction: F1 (64x4 CTAs partial coltile sums) -> F2 (per-row loss)
// -> F3 (scalar)
// ============================================================================
__global__ void __launch_bounds__(128) k_final1() {
    const int tid = threadIdx.x;
    const int r = blockIdx.x * 128 + tid;
    const int p = blockIdx.y;                 // 16 coltiles per part
    float Sp = 0.f, Sn = 0.f;
    #pragma unroll
    for (int cx = p * 16; cx < p * 16 + 16; cx++) {
        Sp += g_Spos[(size_t)cx * N + r];
        Sn += g_Sneg[(size_t)cx * N + r];
    }
    g_Sp2[(size_t)p * N + r] = Sp;
    g_Sn2[(size_t)p * N + r] = Sn;
}

__global__ void __launch_bounds__(128) k_final2() {
    const int tid = threadIdx.x;
    const int r = blockIdx.x * 128 + tid;
    float Sp = 0.f, Sn = 0.f;
    #pragma unroll
    for (int p = 0; p < 4; p++) {
        Sp += g_Sp2[(size_t)p * N + r];
        Sn += g_Sn2[(size_t)p * N + r];
    }
    const int c = g_card[r];
    float s = (c > 0) ? (logf(Sn) - Sp / (float)c) : 0.f;
    for (int o = 16; o; o >>= 1) s += __shfl_xor_sync(~0u, s, o);
    __shared__ float red[4];
    if ((tid & 31) == 0) red[tid >> 5] = s;
    __syncthreads();
    if (tid == 0) g_red[blockIdx.x] = red[0] + red[1] + red[2] + red[3];
}

__global__ void __launch_bounds__(64) k_final3(float* out) {
    const int tid = threadIdx.x;
    float s = g_red[tid];
    for (int o = 16; o; o >>= 1) s += __shfl_xor_sync(~0u, s, o);
    __shared__ float r2[2];
    if ((tid & 31) == 0) r2[tid >> 5] = s;
    __syncthreads();
    if (tid == 0) out[0] = (r2[0] + r2[1]) * (1.0f / (float)N);
}

// ============================================================================
// Launch
// ============================================================================
extern "C" void kernel_launch(void* const* d_in, const int* in_sizes, int n_in,
                              void* d_out, int out_size) {
    (void)in_sizes; (void)n_in; (void)out_size;
    const float* features = (const float*)d_in[0];
    const int*   pos      = (const int*)d_in[1];
    const int*   neg      = (const int*)d_in[2];
    float*       out      = (float*)d_out;

    cudaFuncSetAttribute(k_main, cudaFuncAttributeMaxDynamicSharedMemorySize,
                         SMEM_BYTES);

    k_normalize<<<N, 256>>>(features);
    k_main<<<NTRI, 256, SMEM_BYTES>>>(pos, neg);
    k_final1<<<dim3(64, 4), 128>>>();
    k_final2<<<64, 128>>>();
    k_final3<<<1, 64>>>(out);
}

// round 11
// speedup vs baseline: 1.2726x; 1.2726x over previous
#include <cuda_runtime.h>
#include <cuda_bf16.h>
#include <cstdint>

// ============================================================================
// Problem constants
// ============================================================================
static constexpr int N = 8192;
static constexpr int D = 512;
static constexpr int BM = 128;              // rows per CTA tile
static constexpr int BN = 128;              // cols per CTA tile
static constexpr int BK = 64;               // k per stage
static constexpr int STAGES = 4;
static constexpr int CTILES = N / BN;       // 64 column tiles
static constexpr int NTRI = CTILES * (CTILES + 1) / 2;  // 2080 upper-tri tiles
static constexpr int WPR = N / 32;          // bitmask words per row = 256

static constexpr float CEXP = 20.609929365128333f;      // (1/T)*log2(e), T=0.07

// ============================================================================
// Device scratch (static — no allocation allowed)
// ============================================================================
__device__ __align__(16) __nv_bfloat16 g_fn[N * D];     // normalized features, bf16
__device__ __align__(16) unsigned g_posbits[N * WPR];   // bitpacked masks (diag cleared)
__device__ __align__(16) unsigned g_negbits[N * WPR];
__device__ int   g_card[N];
__device__ float g_Spos[CTILES * N];                    // per-(coltile,row) partials
__device__ float g_Sneg[CTILES * N];
__device__ float g_Sp2[4 * N];                          // final-reduce stage
__device__ float g_Sn2[4 * N];
__device__ float g_red[64];

// ============================================================================
// Helpers (baseline sm_80+ PTX only — NO tcgen05, target is plain sm_103)
// ============================================================================
__device__ __forceinline__ uint32_t smem_u32(const void* p) {
    uint32_t a;
    asm("{ .reg .u64 t; cvta.to.shared.u64 t, %1; cvt.u32.u64 %0, t; }"
        : "=r"(a) : "l"(p));
    return a;
}

__device__ __forceinline__ float ex2f(float x) {
    float y; asm("ex2.approx.ftz.f32 %0, %1;" : "=f"(y) : "f"(x)); return y;
}

#define SW128(o) ((o) ^ (((o) >> 3) & 0x70))

__device__ __forceinline__ void cp16(uint32_t saddr, const void* g) {
    asm volatile("cp.async.cg.shared.global [%0], [%1], 16;"
                 :: "r"(saddr), "l"(g) : "memory");
}

__device__ __forceinline__ void ldsm4(uint32_t* r, uint32_t addr) {
    asm volatile("ldmatrix.sync.aligned.m8n8.x4.shared.b16 {%0,%1,%2,%3}, [%4];"
                 : "=r"(r[0]), "=r"(r[1]), "=r"(r[2]), "=r"(r[3]) : "r"(addr));
}

__device__ __forceinline__ void mma16816(float* c, const uint32_t* a,
                                         uint32_t b0, uint32_t b1) {
    asm volatile(
        "mma.sync.aligned.m16n8k16.row.col.f32.bf16.bf16.f32 "
        "{%0,%1,%2,%3}, {%4,%5,%6,%7}, {%8,%9}, {%0,%1,%2,%3};"
        : "+f"(c[0]), "+f"(c[1]), "+f"(c[2]), "+f"(c[3])
        : "r"(a[0]), "r"(a[1]), "r"(a[2]), "r"(a[3]), "r"(b0), "r"(b1));
}

// ============================================================================
// Kernel A: row-normalize features -> bf16
// ============================================================================
__global__ void __launch_bounds__(256) k_normalize(const float* __restrict__ f) {
    int row = blockIdx.x, tid = threadIdx.x;
    float a = f[row * D + tid];
    float b = f[row * D + 256 + tid];
    float s = a * a + b * b;
    for (int o = 16; o; o >>= 1) s += __shfl_xor_sync(~0u, s, o);
    __shared__ float red[8];
    __shared__ float s_inv;
    if ((tid & 31) == 0) red[tid >> 5] = s;
    __syncthreads();
    if (tid == 0) {
        float t = 0.f;
        #pragma unroll
        for (int i = 0; i < 8; i++) t += red[i];
        float n = fmaxf(sqrtf(t), 1e-8f);
        s_inv = 1.0f / n;
    }
    __syncthreads();
    float inv = s_inv;
    g_fn[row * D + tid]       = __float2bfloat16(a * inv);
    g_fn[row * D + 256 + tid] = __float2bfloat16(b * inv);
}

// ============================================================================
// Kernel P: bitpack masks (ballot), clear diagonal, compute cardinality
// ============================================================================
__global__ void __launch_bounds__(256) k_bitpack(const int* __restrict__ pos,
                                                 const int* __restrict__ neg) {
    int row = blockIdx.x, tid = threadIdx.x;
    int warp = tid >> 5, lane = tid & 31;
    __shared__ int s_card;
    if (tid == 0) s_card = 0;
    __syncthreads();
    int local = 0;
    #pragma unroll 4
    for (int i = 0; i < 32; i++) {
        int w = i * 8 + warp;
        int c = w * 32 + lane;
        unsigned pb = __ballot_sync(~0u, pos[(size_t)row * N + c] != 0);
        unsigned nb = __ballot_sync(~0u, neg[(size_t)row * N + c] != 0);
        if ((row >> 5) == w) { unsigned m = ~(1u << (row & 31)); pb &= m; nb &= m; }
        if (lane == 0) {
            g_posbits[row * WPR + w] = pb;
            g_negbits[row * WPR + w] = nb;
            local += __popc(pb);
        }
    }
    if (lane == 0) atomicAdd(&s_card, local);
    __syncthreads();
    if (tid == 0) g_card[row] = s_card;
}

// ============================================================================
// Kernel M: upper-triangle tiles only (sim is symmetric; masks are not, so
//   each off-diagonal tile runs a normal epilogue AND a smem-transposed one).
//   grid NTRI=2080 linear -> (bi <= bj). 512 threads, 16 warps (4m x 4n),
//   warp tile 32x32 -> 4 warps/SMSP for latency hiding (was 2 at 256 thr).
// ============================================================================
static constexpr uint32_t STAGE_BYTES = 32768;          // A 16KB + B 16KB
static constexpr uint32_t OFF_SA = 0;
static constexpr uint32_t OFF_SB = 16384;
static constexpr uint32_t OFF_RED = STAGES * STAGE_BYTES;      // 131072
static constexpr uint32_t SMEM_BYTES = OFF_RED + 2 * 512 * 4;  // 135168
static constexpr int TP = 132;                          // transpose row pitch (floats)

__device__ __forceinline__ void stage_copy(uint32_t sbase, int tid,
                                           int rowbase, int colbase, int kt) {
    const int k0 = kt * BK;
    #pragma unroll
    for (int i = 0; i < 2; i++) {
        int seg = i * 512 + tid;             // 1024 x 16B segs per tile
        int r = seg >> 3, c = seg & 7;       // 128 rows x 8 x 16B (128B/row)
        uint32_t so = SW128((uint32_t)(r * 128 + c * 16));
        cp16(sbase + OFF_SA + so, g_fn + (size_t)(rowbase + r) * D + k0 + c * 8);
        cp16(sbase + OFF_SB + so, g_fn + (size_t)(colbase + r) * D + k0 + c * 8);
    }
}

__global__ void __launch_bounds__(512, 1) k_main() {
    extern __shared__ char smem[];
    const uint32_t smem_base = smem_u32(smem);
    const int tid  = threadIdx.x;
    const int lane = tid & 31;
    const int wid  = tid >> 5;
    const int warp_m = wid & 3;              // 4 warps along m (32 rows each)
    const int warp_n = wid >> 2;             // 4 warps along n (32 cols each)

    // decode linear tile id -> (bi, bj), bi <= bj
    int t = blockIdx.x;
    int bi = (int)(0.5f * (129.0f - sqrtf(16641.0f - 8.0f * (float)t)));
    while (64 * (bi + 1) - ((bi + 1) * bi) / 2 <= t) bi++;
    while (64 * bi - (bi * (bi - 1)) / 2 > t) bi--;
    const int bj = bi + (t - (64 * bi - (bi * (bi - 1)) / 2));
    const int rowbase = bi * BM;
    const int colbase = bj * BN;

    // deterministic reduction matrices: [row 0..127][warp_n 0..3]
    float* sPm = reinterpret_cast<float*>(smem + OFF_RED);
    float* sNm = sPm + 512;
    sPm[tid] = 0.f; sNm[tid] = 0.f;

    // prologue: fill STAGES-1 stages
    #pragma unroll
    for (int s = 0; s < STAGES - 1; s++) {
        stage_copy(smem_base + s * STAGE_BYTES, tid, rowbase, colbase, s);
        asm volatile("cp.async.commit_group;" ::: "memory");
    }

    float acc[2][4][4];
    #pragma unroll
    for (int mi = 0; mi < 2; mi++)
        #pragma unroll
        for (int nj = 0; nj < 4; nj++)
            #pragma unroll
            for (int q = 0; q < 4; q++) acc[mi][nj][q] = 0.f;

    const int la_row  = warp_m * 32 + (lane & 15);   // A ldmatrix row
    const int lb_row  = warp_n * 32 + (lane & 15);   // B ldmatrix row
    const int l_khalf = (lane >> 4) * 16;            // k-half byte offset

    #pragma unroll 1
    for (int kt = 0; kt < D / BK; kt++) {
        asm volatile("cp.async.wait_group %0;" :: "n"(STAGES - 2) : "memory");
        __syncthreads();

        if (kt + STAGES - 1 < D / BK) {
            stage_copy(smem_base + ((kt + STAGES - 1) % STAGES) * STAGE_BYTES,
                       tid, rowbase, colbase, kt + STAGES - 1);
        }
        asm volatile("cp.async.commit_group;" ::: "memory");

        const uint32_t sa = smem_base + (kt % STAGES) * STAGE_BYTES + OFF_SA;
        const uint32_t sb = smem_base + (kt % STAGES) * STAGE_BYTES + OFF_SB;

        #pragma unroll
        for (int kk = 0; kk < BK / 16; kk++) {
            uint32_t a[2][4], b[2][4];
            #pragma unroll
            for (int mi = 0; mi < 2; mi++)
                ldsm4(a[mi], sa + SW128((uint32_t)((la_row + mi * 16) * 128 +
                                                   kk * 32 + l_khalf)));
            #pragma unroll
            for (int np = 0; np < 2; np++)
                ldsm4(b[np], sb + SW128((uint32_t)((lb_row + np * 16) * 128 +
                                                   kk * 32 + l_khalf)));
            #pragma unroll
            for (int mi = 0; mi < 2; mi++)
                #pragma unroll
                for (int nj = 0; nj < 4; nj++)
                    mma16816(acc[mi][nj], a[mi],
                             b[nj >> 1][(nj & 1)], b[nj >> 1][(nj & 1) + 2]);
        }
    }

    // ------------------------------------------------------------------
    // Convert accumulators to p = exp((sim-1)/T) in place
    // ------------------------------------------------------------------
    #pragma unroll
    for (int mi = 0; mi < 2; mi++)
        #pragma unroll
        for (int nj = 0; nj < 4; nj++)
            #pragma unroll
            for (int q = 0; q < 4; q++)
                acc[mi][nj][q] = ex2f(fmaf(acc[mi][nj][q], CEXP, -CEXP));

    // ------------------------------------------------------------------
    // Normal epilogue: masked row sums for rows of block bi, cols block bj.
    // Each warp owns a 32-col window (1 mask word). Deterministic: per
    // (row, warp_n) one smem slot, fixed-order sum afterwards.
    // ------------------------------------------------------------------
    const int wb = (colbase >> 5) + warp_n;
    #pragma unroll
    for (int mi = 0; mi < 2; mi++) {
        #pragma unroll
        for (int rsel = 0; rsel < 2; rsel++) {
            const int lrow = warp_m * 32 + mi * 16 + (lane >> 2) + rsel * 8;
            const int grow = rowbase + lrow;
            const unsigned pword = g_posbits[(size_t)grow * WPR + wb];
            const unsigned nword = g_negbits[(size_t)grow * WPR + wb];
            float sp = 0.f, sn = 0.f;
            #pragma unroll
            for (int nj = 0; nj < 4; nj++) {
                #pragma unroll
                for (int u = 0; u < 2; u++) {
                    float p = acc[mi][nj][rsel * 2 + u];
                    int c32 = nj * 8 + (lane & 3) * 2 + u;
                    sp = fmaf(p, (float)((pword >> c32) & 1u), sp);
                    sn = fmaf(p, (float)((nword >> c32) & 1u), sn);
                }
            }
            sp += __shfl_xor_sync(~0u, sp, 1);
            sp += __shfl_xor_sync(~0u, sp, 2);
            sn += __shfl_xor_sync(~0u, sn, 1);
            sn += __shfl_xor_sync(~0u, sn, 2);
            if ((lane & 3) == 0) {
                sPm[lrow * 4 + warp_n] = sp;    // one writer per slot
                sNm[lrow * 4 + warp_n] = sn;
            }
        }
    }
    asm volatile("cp.async.wait_group 0;" ::: "memory");
    __syncthreads();     // stage smem reads done; sPm/sNm complete
    if (tid < 128) {
        float Sp = sPm[tid * 4] + sPm[tid * 4 + 1] + sPm[tid * 4 + 2] + sPm[tid * 4 + 3];
        float Sn = sNm[tid * 4] + sNm[tid * 4 + 1] + sNm[tid * 4 + 2] + sNm[tid * 4 + 3];
        g_Spos[(size_t)bj * N + rowbase + tid] = Sp;
        g_Sneg[(size_t)bj * N + rowbase + tid] = Sn;
    }

    // ------------------------------------------------------------------
    // Transposed epilogue (off-diagonal tiles): p_ij == p_ji — this tile
    // also provides cols of block bi for rows of block bj. Stage p into
    // smem transposed; 4 threads per column, quad-shuffle reduce.
    // ------------------------------------------------------------------
    if (bi != bj) {
        float* tf = reinterpret_cast<float*>(smem);     // reuse stage area
        #pragma unroll
        for (int mi = 0; mi < 2; mi++)
            #pragma unroll
            for (int rsel = 0; rsel < 2; rsel++) {
                const int r = warp_m * 32 + mi * 16 + (lane >> 2) + rsel * 8;
                #pragma unroll
                for (int nj = 0; nj < 4; nj++)
                    #pragma unroll
                    for (int u = 0; u < 2; u++) {
                        const int c = warp_n * 32 + nj * 8 + (lane & 3) * 2 + u;
                        tf[c * TP + r] = acc[mi][nj][rsel * 2 + u];
                    }
            }
        __syncthreads();
        {
            const int c = tid >> 2;                   // 128 cols x 4 threads
            const int q = tid & 3;                    // 32-row word each
            const int gcol = colbase + c;
            const unsigned pword = g_posbits[(size_t)gcol * WPR + (rowbase >> 5) + q];
            const unsigned nword = g_negbits[(size_t)gcol * WPR + (rowbase >> 5) + q];
            const float* pf = tf + c * TP + q * 32;
            float sp = 0.f, sn = 0.f;
            #pragma unroll 8
            for (int b = 0; b < 32; b++) {
                float p = pf[b];
                sp = fmaf(p, (float)((pword >> b) & 1u), sp);
                sn = fmaf(p, (float)((nword >> b) & 1u), sn);
            }
            sp += __shfl_xor_sync(~0u, sp, 1);
            sp += __shfl_xor_sync(~0u, sp, 2);
            sn += __shfl_xor_sync(~0u, sn, 1);
            sn += __shfl_xor_sync(~0u, sn, 2);
            if ((tid & 3) == 0) {
                g_Spos[(size_t)bi * N + gcol] = sp;
                g_Sneg[(size_t)bi * N + gcol] = sn;
            }
        }
    }
}

// ============================================================================
// Final reduction: F1 (64x4 CTAs partial coltile sums) -> F2 (per-row loss)
// -> F3 (scalar)
// ============================================================================
__global__ void __launch_bounds__(128) k_final1() {
    const int tid = threadIdx.x;
    const int r = blockIdx.x * 128 + tid;
    const int p = blockIdx.y;                 // 16 coltiles per part
    float Sp = 0.f, Sn = 0.f;
    #pragma unroll
    for (int cx = p * 16; cx < p * 16 + 16; cx++) {
        Sp += g_Spos[(size_t)cx * N + r];
        Sn += g_Sneg[(size_t)cx * N + r];
    }
    g_Sp2[(size_t)p * N + r] = Sp;
    g_Sn2[(size_t)p * N + r] = Sn;
}

__global__ void __launch_bounds__(128) k_final2() {
    const int tid = threadIdx.x;
    const int r = blockIdx.x * 128 + tid;
    float Sp = 0.f, Sn = 0.f;
    #pragma unroll
    for (int p = 0; p < 4; p++) {
        Sp += g_Sp2[(size_t)p * N + r];
        Sn += g_Sn2[(size_t)p * N + r];
    }
    const int c = g_card[r];
    float s = (c > 0) ? (logf(Sn) - Sp / (float)c) : 0.f;
    for (int o = 16; o; o >>= 1) s += __shfl_xor_sync(~0u, s, o);
    __shared__ float red[4];
    if ((tid & 31) == 0) red[tid >> 5] = s;
    __syncthreads();
    if (tid == 0) g_red[blockIdx.x] = red[0] + red[1] + red[2] + red[3];
}

__global__ void __launch_bounds__(64) k_final3(float* out) {
    const int tid = threadIdx.x;
    float s = g_red[tid];
    for (int o = 16; o; o >>= 1) s += __shfl_xor_sync(~0u, s, o);
    __shared__ float r2[2];
    if ((tid & 31) == 0) r2[tid >> 5] = s;
    __syncthreads();
    if (tid == 0) out[0] = (r2[0] + r2[1]) * (1.0f / (float)N);
}

// ============================================================================
// Launch
// ============================================================================
extern "C" void kernel_launch(void* const* d_in, const int* in_sizes, int n_in,
                              void* d_out, int out_size) {
    (void)in_sizes; (void)n_in; (void)out_size;
    const float* features = (const float*)d_in[0];
    const int*   pos      = (const int*)d_in[1];
    const int*   neg      = (const int*)d_in[2];
    float*       out      = (float*)d_out;

    cudaFuncSetAttribute(k_main, cudaFuncAttributeMaxDynamicSharedMemorySize,
                         SMEM_BYTES);

    k_normalize<<<N, 256>>>(features);
    k_bitpack<<<N, 256>>>(pos, neg);
    k_main<<<NTRI, 512, SMEM_BYTES>>>();
    k_final1<<<dim3(64, 4), 128>>>();
    k_final2<<<64, 128>>>();
    k_final3<<<1, 64>>>(out);
}

// round 15
// speedup vs baseline: 1.3196x; 1.0369x over previous
#include <cuda_runtime.h>
#include <cuda_bf16.h>
#include <cstdint>

// ============================================================================
// Problem constants
// ============================================================================
static constexpr int N = 8192;
static constexpr int D = 512;
static constexpr int BM = 128;              // rows per CTA tile
static constexpr int BN = 128;              // cols per CTA tile
static constexpr int BK = 64;               // k per stage
static constexpr int STAGES = 4;
static constexpr int CTILES = N / BN;       // 64 column tiles
static constexpr int NTRI = CTILES * (CTILES + 1) / 2;  // 2080 upper-tri tiles

static constexpr float CEXP = 20.609929365128333f;      // (1/T)*log2(e), T=0.07

// ============================================================================
// Device scratch (static — no allocation allowed)
// ============================================================================
__device__ __align__(16) __nv_bfloat16 g_fn[N * D];     // normalized features, bf16
__device__ int   g_card[N];
__device__ float g_Spos[CTILES * N];                    // per-(coltile,row) partials
__device__ float g_Sneg[CTILES * N];
__device__ float g_Sp2[4 * N];                          // final-reduce stage
__device__ float g_Sn2[4 * N];
__device__ float g_red[64];

// ============================================================================
// Helpers (baseline sm_80+ PTX only — NO tcgen05, target is plain sm_103)
// ============================================================================
__device__ __forceinline__ uint32_t smem_u32(const void* p) {
    uint32_t a;
    asm("{ .reg .u64 t; cvta.to.shared.u64 t, %1; cvt.u32.u64 %0, t; }"
        : "=r"(a) : "l"(p));
    return a;
}

__device__ __forceinline__ float ex2f(float x) {
    float y; asm("ex2.approx.ftz.f32 %0, %1;" : "=f"(y) : "f"(x)); return y;
}

#define SW128(o) ((o) ^ (((o) >> 3) & 0x70))

__device__ __forceinline__ void cp16(uint32_t saddr, const void* g) {
    asm volatile("cp.async.cg.shared.global [%0], [%1], 16;"
                 :: "r"(saddr), "l"(g) : "memory");
}

__device__ __forceinline__ void ldsm4(uint32_t* r, uint32_t addr) {
    asm volatile("ldmatrix.sync.aligned.m8n8.x4.shared.b16 {%0,%1,%2,%3}, [%4];"
                 : "=r"(r[0]), "=r"(r[1]), "=r"(r[2]), "=r"(r[3]) : "r"(addr));
}

__device__ __forceinline__ void mma16816(float* c, const uint32_t* a,
                                         uint32_t b0, uint32_t b1) {
    asm volatile(
        "mma.sync.aligned.m16n8k16.row.col.f32.bf16.bf16.f32 "
        "{%0,%1,%2,%3}, {%4,%5,%6,%7}, {%8,%9}, {%0,%1,%2,%3};"
        : "+f"(c[0]), "+f"(c[1]), "+f"(c[2]), "+f"(c[3])
        : "r"(a[0]), "r"(a[1]), "r"(a[2]), "r"(a[3]), "r"(b0), "r"(b1));
}

// ============================================================================
// Kernel A: row-normalize features -> bf16 (+ zero g_card for this replay)
// ============================================================================
__global__ void __launch_bounds__(256) k_normalize(const float* __restrict__ f) {
    int row = blockIdx.x, tid = threadIdx.x;
    float a = f[row * D + tid];
    float b = f[row * D + 256 + tid];
    float s = a * a + b * b;
    for (int o = 16; o; o >>= 1) s += __shfl_xor_sync(~0u, s, o);
    __shared__ float red[8];
    __shared__ float s_inv;
    if ((tid & 31) == 0) red[tid >> 5] = s;
    __syncthreads();
    if (tid == 0) {
        float t = 0.f;
        #pragma unroll
        for (int i = 0; i < 8; i++) t += red[i];
        float n = fmaxf(sqrtf(t), 1e-8f);
        s_inv = 1.0f / n;
        g_card[row] = 0;                      // reset for k_main's atomics
    }
    __syncthreads();
    float inv = s_inv;
    g_fn[row * D + tid]       = __float2bfloat16(a * inv);
    g_fn[row * D + 256 + tid] = __float2bfloat16(b * inv);
}

// ============================================================================
// Kernel M: upper-triangle tiles only (sim is symmetric; masks are not, so
//   each off-diagonal tile runs a normal epilogue AND a smem-transposed one).
//   Masks are read RAW (int32) in the epilogues — no separate bitpack pass;
//   their DRAM traffic overlaps with other SMs' mainloop compute.
//   grid NTRI=2080 linear -> (bi <= bj). 512 threads, 16 warps (4m x 4n).
// ============================================================================
static constexpr uint32_t STAGE_BYTES = 32768;          // A 16KB + B 16KB
static constexpr uint32_t OFF_SA = 0;
static constexpr uint32_t OFF_SB = 16384;
static constexpr uint32_t OFF_RED = STAGES * STAGE_BYTES;      // 131072
static constexpr uint32_t SMEM_BYTES = OFF_RED + 2 * 512 * 4;  // 135168
static constexpr int TP = 132;                          // transpose row pitch (floats)

__device__ __forceinline__ void stage_copy(uint32_t sbase, int tid,
                                           int rowbase, int colbase, int kt) {
    const int k0 = kt * BK;
    #pragma unroll
    for (int i = 0; i < 2; i++) {
        int seg = i * 512 + tid;             // 1024 x 16B segs per tile
        int r = seg >> 3, c = seg & 7;       // 128 rows x 8 x 16B (128B/row)
        uint32_t so = SW128((uint32_t)(r * 128 + c * 16));
        cp16(sbase + OFF_SA + so, g_fn + (size_t)(rowbase + r) * D + k0 + c * 8);
        cp16(sbase + OFF_SB + so, g_fn + (size_t)(colbase + r) * D + k0 + c * 8);
    }
}

__global__ void __launch_bounds__(512, 1) k_main(const int* __restrict__ posm,
                                                 const int* __restrict__ negm) {
    extern __shared__ char smem[];
    const uint32_t smem_base = smem_u32(smem);
    const int tid  = threadIdx.x;
    const int lane = tid & 31;
    const int wid  = tid >> 5;
    const int warp_m = wid & 3;              // 4 warps along m (32 rows each)
    const int warp_n = wid >> 2;             // 4 warps along n (32 cols each)

    // decode linear tile id -> (bi, bj), bi <= bj
    int t = blockIdx.x;
    int bi = (int)(0.5f * (129.0f - sqrtf(16641.0f - 8.0f * (float)t)));
    while (64 * (bi + 1) - ((bi + 1) * bi) / 2 <= t) bi++;
    while (64 * bi - (bi * (bi - 1)) / 2 > t) bi--;
    const int bj = bi + (t - (64 * bi - (bi * (bi - 1)) / 2));
    const int rowbase = bi * BM;
    const int colbase = bj * BN;

    // deterministic reduction matrices: [row 0..127][warp_n 0..3]
    float* sPm = reinterpret_cast<float*>(smem + OFF_RED);
    float* sNm = sPm + 512;
    sPm[tid] = 0.f; sNm[tid] = 0.f;

    // prologue: fill STAGES-1 stages
    #pragma unroll
    for (int s = 0; s < STAGES - 1; s++) {
        stage_copy(smem_base + s * STAGE_BYTES, tid, rowbase, colbase, s);
        asm volatile("cp.async.commit_group;" ::: "memory");
    }

    float acc[2][4][4];
    #pragma unroll
    for (int mi = 0; mi < 2; mi++)
        #pragma unroll
        for (int nj = 0; nj < 4; nj++)
            #pragma unroll
            for (int q = 0; q < 4; q++) acc[mi][nj][q] = 0.f;

    const int la_row  = warp_m * 32 + (lane & 15);   // A ldmatrix row
    const int lb_row  = warp_n * 32 + (lane & 15);   // B ldmatrix row
    const int l_khalf = (lane >> 4) * 16;            // k-half byte offset

    #pragma unroll 1
    for (int kt = 0; kt < D / BK; kt++) {
        asm volatile("cp.async.wait_group %0;" :: "n"(STAGES - 2) : "memory");
        __syncthreads();

        if (kt + STAGES - 1 < D / BK) {
            stage_copy(smem_base + ((kt + STAGES - 1) % STAGES) * STAGE_BYTES,
                       tid, rowbase, colbase, kt + STAGES - 1);
        }
        asm volatile("cp.async.commit_group;" ::: "memory");

        const uint32_t sa = smem_base + (kt % STAGES) * STAGE_BYTES + OFF_SA;
        const uint32_t sb = smem_base + (kt % STAGES) * STAGE_BYTES + OFF_SB;

        #pragma unroll
        for (int kk = 0; kk < BK / 16; kk++) {
            uint32_t a[2][4], b[2][4];
            #pragma unroll
            for (int mi = 0; mi < 2; mi++)
                ldsm4(a[mi], sa + SW128((uint32_t)((la_row + mi * 16) * 128 +
                                                   kk * 32 + l_khalf)));
            #pragma unroll
            for (int np = 0; np < 2; np++)
                ldsm4(b[np], sb + SW128((uint32_t)((lb_row + np * 16) * 128 +
                                                   kk * 32 + l_khalf)));
            #pragma unroll
            for (int mi = 0; mi < 2; mi++)
                #pragma unroll
                for (int nj = 0; nj < 4; nj++)
                    mma16816(acc[mi][nj], a[mi],
                             b[nj >> 1][(nj & 1)], b[nj >> 1][(nj & 1) + 2]);
        }
    }

    // ------------------------------------------------------------------
    // Convert accumulators to p = exp((sim-1)/T) in place
    // ------------------------------------------------------------------
    #pragma unroll
    for (int mi = 0; mi < 2; mi++)
        #pragma unroll
        for (int nj = 0; nj < 4; nj++)
            #pragma unroll
            for (int q = 0; q < 4; q++)
                acc[mi][nj][q] = ex2f(fmaf(acc[mi][nj][q], CEXP, -CEXP));

    // ------------------------------------------------------------------
    // Normal epilogue: rows of block bi, cols of block bj. Raw int32 mask
    // reads (int2), diagonal excluded explicitly, card via int atomics.
    // ------------------------------------------------------------------
    const int colw = colbase + warp_n * 32 + (lane & 3) * 2;
    #pragma unroll
    for (int mi = 0; mi < 2; mi++) {
        #pragma unroll
        for (int rsel = 0; rsel < 2; rsel++) {
            const int lrow = warp_m * 32 + mi * 16 + (lane >> 2) + rsel * 8;
            const int grow = rowbase + lrow;
            const int* prow = posm + (size_t)grow * N + colw;
            const int* nrow = negm + (size_t)grow * N + colw;
            float sp = 0.f, sn = 0.f;
            int cnt = 0;
            #pragma unroll
            for (int nj = 0; nj < 4; nj++) {
                const int2 pv = *reinterpret_cast<const int2*>(prow + nj * 8);
                const int2 nv = *reinterpret_cast<const int2*>(nrow + nj * 8);
                #pragma unroll
                for (int u = 0; u < 2; u++) {
                    const int gcol = colw + nj * 8 + u;
                    const int pm = ((u ? pv.y : pv.x) != 0) & (gcol != grow);
                    const int nm = ((u ? nv.y : nv.x) != 0) & (gcol != grow);
                    float p = acc[mi][nj][rsel * 2 + u];
                    sp = fmaf(p, (float)pm, sp);
                    sn = fmaf(p, (float)nm, sn);
                    cnt += pm;
                }
            }
            sp += __shfl_xor_sync(~0u, sp, 1);
            sp += __shfl_xor_sync(~0u, sp, 2);
            sn += __shfl_xor_sync(~0u, sn, 1);
            sn += __shfl_xor_sync(~0u, sn, 2);
            cnt += __shfl_xor_sync(~0u, cnt, 1);
            cnt += __shfl_xor_sync(~0u, cnt, 2);
            if ((lane & 3) == 0) {
                sPm[lrow * 4 + warp_n] = sp;    // one writer per slot
                sNm[lrow * 4 + warp_n] = sn;
                atomicAdd(&g_card[grow], cnt);  // int: deterministic
            }
        }
    }
    asm volatile("cp.async.wait_group 0;" ::: "memory");
    __syncthreads();     // stage smem reads done; sPm/sNm complete
    if (tid < 128) {
        float Sp = sPm[tid * 4] + sPm[tid * 4 + 1] + sPm[tid * 4 + 2] + sPm[tid * 4 + 3];
        float Sn = sNm[tid * 4] + sNm[tid * 4 + 1] + sNm[tid * 4 + 2] + sNm[tid * 4 + 3];
        g_Spos[(size_t)bj * N + rowbase + tid] = Sp;
        g_Sneg[(size_t)bj * N + rowbase + tid] = Sn;
    }

    // ------------------------------------------------------------------
    // Transposed epilogue (off-diagonal tiles): p_ij == p_ji — this tile
    // also provides cols of block bi for rows of block bj. Stage p into
    // smem transposed; 4 threads per column, int4 mask loads (coalesced).
    // No diagonal here (bi != bj).
    // ------------------------------------------------------------------
    if (bi != bj) {
        float* tf = reinterpret_cast<float*>(smem);     // reuse stage area
        #pragma unroll
        for (int mi = 0; mi < 2; mi++)
            #pragma unroll
            for (int rsel = 0; rsel < 2; rsel++) {
                const int r = warp_m * 32 + mi * 16 + (lane >> 2) + rsel * 8;
                #pragma unroll
                for (int nj = 0; nj < 4; nj++)
                    #pragma unroll
                    for (int u = 0; u < 2; u++) {
                        const int c = warp_n * 32 + nj * 8 + (lane & 3) * 2 + u;
                        tf[c * TP + r] = acc[mi][nj][rsel * 2 + u];
                    }
            }
        __syncthreads();
        {
            const int c = tid >> 2;                   // 128 cols x 4 threads
            const int q = tid & 3;                    // 32-row chunk each
            const int gcol = colbase + c;
            const int* pr = posm + (size_t)gcol * N + rowbase + q * 32;
            const int* nr = negm + (size_t)gcol * N + rowbase + q * 32;
            const float* pf = tf + c * TP + q * 32;
            float sp = 0.f, sn = 0.f;
            int cnt = 0;
            #pragma unroll
            for (int j = 0; j < 8; j++) {
                const int4 pv = reinterpret_cast<const int4*>(pr)[j];
                const int4 nv = reinterpret_cast<const int4*>(nr)[j];
                const int pe[4] = {pv.x != 0, pv.y != 0, pv.z != 0, pv.w != 0};
                const int ne[4] = {nv.x != 0, nv.y != 0, nv.z != 0, nv.w != 0};
                #pragma unroll
                for (int e = 0; e < 4; e++) {
                    float p = pf[j * 4 + e];
                    sp = fmaf(p, (float)pe[e], sp);
                    sn = fmaf(p, (float)ne[e], sn);
                    cnt += pe[e];
                }
            }
            sp += __shfl_xor_sync(~0u, sp, 1);
            sp += __shfl_xor_sync(~0u, sp, 2);
            sn += __shfl_xor_sync(~0u, sn, 1);
            sn += __shfl_xor_sync(~0u, sn, 2);
            cnt += __shfl_xor_sync(~0u, cnt, 1);
            cnt += __shfl_xor_sync(~0u, cnt, 2);
            if ((tid & 3) == 0) {
                g_Spos[(size_t)bi * N + gcol] = sp;
                g_Sneg[(size_t)bi * N + gcol] = sn;
                atomicAdd(&g_card[gcol], cnt);
            }
        }
    }
}

// ============================================================================
// Final reduction: F1 (64x4 CTAs partial coltile sums) -> F2 (per-row loss)
// -> F3 (scalar)
// ============================================================================
__global__ void __launch_bounds__(128) k_final1() {
    const int tid = threadIdx.x;
    const int r = blockIdx.x * 128 + tid;
    const int p = blockIdx.y;                 // 16 coltiles per part
    float Sp = 0.f, Sn = 0.f;
    #pragma unroll
    for (int cx = p * 16; cx < p * 16 + 16; cx++) {
        Sp += g_Spos[(size_t)cx * N + r];
        Sn += g_Sneg[(size_t)cx * N + r];
    }
    g_Sp2[(size_t)p * N + r] = Sp;
    g_Sn2[(size_t)p * N + r] = Sn;
}

__global__ void __launch_bounds__(128) k_final2() {
    const int tid = threadIdx.x;
    const int r = blockIdx.x * 128 + tid;
    float Sp = 0.f, Sn = 0.f;
    #pragma unroll
    for (int p = 0; p < 4; p++) {
        Sp += g_Sp2[(size_t)p * N + r];
        Sn += g_Sn2[(size_t)p * N + r];
    }
    const int c = g_card[r];
    float s = (c > 0) ? (logf(Sn) - Sp / (float)c) : 0.f;
    for (int o = 16; o; o >>= 1) s += __shfl_xor_sync(~0u, s, o);
    __shared__ float red[4];
    if ((tid & 31) == 0) red[tid >> 5] = s;
    __syncthreads();
    if (tid == 0) g_red[blockIdx.x] = red[0] + red[1] + red[2] + red[3];
}

__global__ void __launch_bounds__(64) k_final3(float* out) {
    const int tid = threadIdx.x;
    float s = g_red[tid];
    for (int o = 16; o; o >>= 1) s += __shfl_xor_sync(~0u, s, o);
    __shared__ float r2[2];
    if ((tid & 31) == 0) r2[tid >> 5] = s;
    __syncthreads();
    if (tid == 0) out[0] = (r2[0] + r2[1]) * (1.0f / (float)N);
}

// ============================================================================
// Launch
// ============================================================================
extern "C" void kernel_launch(void* const* d_in, const int* in_sizes, int n_in,
                              void* d_out, int out_size) {
    (void)in_sizes; (void)n_in; (void)out_size;
    const float* features = (const float*)d_in[0];
    const int*   pos      = (const int*)d_in[1];
    const int*   neg      = (const int*)d_in[2];
    float*       out      = (float*)d_out;

    cudaFuncSetAttribute(k_main, cudaFuncAttributeMaxDynamicSharedMemorySize,
                         SMEM_BYTES);

    k_normalize<<<N, 256>>>(features);
    k_main<<<NTRI, 512, SMEM_BYTES>>>(pos, neg);
    k_final1<<<dim3(64, 4), 128>>>();
    k_final2<<<64, 128>>>();
    k_final3<<<1, 64>>>(out);
}